// round 9
// baseline (speedup 1.0000x reference)
#include <cuda_runtime.h>
#include <stdint.h>

// Problem dims (compile-time)
#define HID   1024
#define SEQ   2048
#define BATCH 4
#define NH    16
#define NG    1024
#define M_TOT (BATCH * SEQ)   // 8192
#define SCALE 0.125f          // 1/sqrt(64)

// Scratch buffers (static device arrays — no allocs)
__device__ float g_q[(size_t)M_TOT * HID];
__device__ float g_k[(size_t)M_TOT * HID];
__device__ float g_v[(size_t)M_TOT * HID];
__device__ float g_ctx[(size_t)M_TOT * HID];
__device__ float g_x[(size_t)M_TOT * HID];     // tf32-rounded input
__device__ float g_wq[(size_t)HID * HID];      // tf32-rounded weights
__device__ float g_wk[(size_t)HID * HID];
__device__ float g_wv[(size_t)HID * HID];
__device__ float g_wo[(size_t)HID * HID];

// ===========================================================================
// helpers
// ===========================================================================
__device__ __forceinline__ uint32_t smem_u32(const void* p) {
    uint32_t a;
    asm("{ .reg .u64 t; cvta.to.shared.u64 t, %1; cvt.u32.u64 %0, t; }"
        : "=r"(a) : "l"(p));
    return a;
}

__device__ __forceinline__ void cp16(uint32_t dst, const void* src) {
    asm volatile("cp.async.cg.shared.global [%0], [%1], 16;\n"
                 :: "r"(dst), "l"(src));
}
#define CP_COMMIT() asm volatile("cp.async.commit_group;\n" ::: "memory")
#define CP_WAIT0()  asm volatile("cp.async.wait_group 0;\n" ::: "memory")
#define CP_WAIT1()  asm volatile("cp.async.wait_group 1;\n" ::: "memory")

__device__ __forceinline__ uint32_t f2tf32(float x) {
    uint32_t r;
    asm("cvt.rna.tf32.f32 %0, %1;" : "=r"(r) : "f"(x));
    return r;
}

// mma.sync m16n8k8 tf32: D += A(16x8 row) * B(8x8 col)
__device__ __forceinline__ void mma_tf32(float* c, const uint32_t* a, const uint32_t* b) {
    asm volatile(
        "mma.sync.aligned.m16n8k8.row.col.f32.tf32.tf32.f32 "
        "{%0,%1,%2,%3}, {%4,%5,%6,%7}, {%8,%9}, {%0,%1,%2,%3};\n"
        : "+f"(c[0]), "+f"(c[1]), "+f"(c[2]), "+f"(c[3])
        : "r"(a[0]), "r"(a[1]), "r"(a[2]), "r"(a[3]), "r"(b[0]), "r"(b[1]));
}

// ===========================================================================
// pre-pass: round fp32 tensors to tf32 (rna), stored as fp32 bits
// ===========================================================================
__global__ __launch_bounds__(256) void round_tf32_kernel(
    const float* __restrict__ in, float* __restrict__ out, int n4)
{
    const int i = blockIdx.x * 256 + threadIdx.x;
    if (i < n4) {
        float4 v = ((const float4*)in)[i];
        float4 r;
        r.x = __uint_as_float(f2tf32(v.x));
        r.y = __uint_as_float(f2tf32(v.y));
        r.z = __uint_as_float(f2tf32(v.z));
        r.w = __uint_as_float(f2tf32(v.w));
        ((float4*)out)[i] = r;
    }
}

__global__ __launch_bounds__(256) void round_w_kernel(
    const float* __restrict__ w0, const float* __restrict__ w1,
    const float* __restrict__ w2, const float* __restrict__ w3,
    float* __restrict__ o0, float* __restrict__ o1,
    float* __restrict__ o2, float* __restrict__ o3, int n4)
{
    const int z = blockIdx.y;
    const float* in = z == 0 ? w0 : (z == 1 ? w1 : (z == 2 ? w2 : w3));
    float* out      = z == 0 ? o0 : (z == 1 ? o1 : (z == 2 ? o2 : o3));
    const int i = blockIdx.x * 256 + threadIdx.x;
    if (i < n4) {
        float4 v = ((const float4*)in)[i];
        float4 r;
        r.x = __uint_as_float(f2tf32(v.x));
        r.y = __uint_as_float(f2tf32(v.y));
        r.z = __uint_as_float(f2tf32(v.z));
        r.w = __uint_as_float(f2tf32(v.w));
        ((float4*)out)[i] = r;
    }
}

// ===========================================================================
// tf32 mma.sync GEMM (NT), 3-stage cp.async pipeline, fused over blockIdx.z.
// 128 threads / 4 warps, warp tile 64x64 (4 m-frags x 8 n-frags).
// C_z[m,n] = sum_k A[m,k] * W_z[n,k] + bias_z[n]. A, W pre-rounded tf32.
// ===========================================================================
#define KC        32
#define NCHUNK    (HID / KC)             // 32
#define GPITCH    36
#define OP_FLOATS (128 * GPITCH)
#define STAGE_FLOATS (2 * OP_FLOATS)     // 9216 floats
#define GEMM_SMEM (3 * STAGE_FLOATS * 4) // 110592 B

__global__ __launch_bounds__(128) void gemm_tf32_3(
    const float* __restrict__ A,
    const float* __restrict__ W0, const float* __restrict__ W1,
    const float* __restrict__ W2,
    const float* __restrict__ b0, const float* __restrict__ b1,
    const float* __restrict__ b2,
    float* __restrict__ C0, float* __restrict__ C1, float* __restrict__ C2,
    int round_out)
{
    extern __shared__ __align__(16) float smem[];
    const int tid  = threadIdx.x;
    const int wid  = tid >> 5;
    const int lane = tid & 31;
    const int bn   = blockIdx.x;
    const int bm   = blockIdx.y;
    const int z    = blockIdx.z;

    const float* W    = z == 0 ? W0 : (z == 1 ? W1 : W2);
    const float* bias = z == 0 ? b0 : (z == 1 ? b1 : b2);
    float* C          = z == 0 ? C0 : (z == 1 ? C1 : C2);

    const int wy = wid >> 1;       // m half: rows wy*64..+63
    const int wx = wid & 1;        // n half: cols wx*64..+63
    const int qid = lane >> 2;
    const int rid = lane & 3;

    const uint32_t sbase = smem_u32(smem);
    const float* Ab = A + (size_t)bm * 128 * HID;
    const float* Wb = W + (size_t)bn * 128 * HID;

    auto load_chunk = [&](int c, int s) {
        const uint32_t sa = sbase + (uint32_t)(s * STAGE_FLOATS) * 4u;
        const uint32_t sb = sa + (uint32_t)OP_FLOATS * 4u;
        const int k0 = c * KC;
#pragma unroll
        for (int p = 0; p < 8; p++) {
            const int idx = tid + p * 128;
            const int r  = idx >> 3;
            const int cc = idx & 7;
            const uint32_t off = (uint32_t)(r * GPITCH + cc * 4) * 4u;
            const size_t gsrc = (size_t)r * HID + k0 + cc * 4;
            cp16(sa + off, Ab + gsrc);
            cp16(sb + off, Wb + gsrc);
        }
        CP_COMMIT();
    };

    float cacc[4][8][4];
#pragma unroll
    for (int mt = 0; mt < 4; mt++)
#pragma unroll
        for (int nt = 0; nt < 8; nt++)
#pragma unroll
            for (int e = 0; e < 4; e++) cacc[mt][nt][e] = 0.0f;

    load_chunk(0, 0);
    load_chunk(1, 1);

    for (int c = 0; c < NCHUNK; c++) {
        if (c == NCHUNK - 1) { CP_WAIT0(); } else { CP_WAIT1(); }
        __syncthreads();
        if (c + 2 < NCHUNK) load_chunk(c + 2, (c + 2) % 3);

        const float* As = smem + (c % 3) * STAGE_FLOATS;
        const float* Bs = As + OP_FLOATS;

#pragma unroll
        for (int ks = 0; ks < 4; ks++) {
            const int k0 = ks * 8;
            uint32_t afr[4][4];
#pragma unroll
            for (int mt = 0; mt < 4; mt++) {
                const int row = wy * 64 + mt * 16 + qid;
                afr[mt][0] = __float_as_uint(As[(row    ) * GPITCH + k0 + rid    ]);
                afr[mt][1] = __float_as_uint(As[(row + 8) * GPITCH + k0 + rid    ]);
                afr[mt][2] = __float_as_uint(As[(row    ) * GPITCH + k0 + rid + 4]);
                afr[mt][3] = __float_as_uint(As[(row + 8) * GPITCH + k0 + rid + 4]);
            }
            uint32_t bfr[8][2];
#pragma unroll
            for (int nt = 0; nt < 8; nt++) {
                const int n = wx * 64 + nt * 8 + qid;
                bfr[nt][0] = __float_as_uint(Bs[n * GPITCH + k0 + rid    ]);
                bfr[nt][1] = __float_as_uint(Bs[n * GPITCH + k0 + rid + 4]);
            }
#pragma unroll
            for (int mt = 0; mt < 4; mt++)
#pragma unroll
                for (int nt = 0; nt < 8; nt++)
                    mma_tf32(cacc[mt][nt], afr[mt], bfr[nt]);
        }
        // stage (c%3) is only overwritten by the load issued at iteration
        // c+1, which happens after its leading barrier.
    }

#pragma unroll
    for (int mt = 0; mt < 4; mt++) {
        const int row0 = bm * 128 + wy * 64 + mt * 16 + qid;
#pragma unroll
        for (int nt = 0; nt < 8; nt++) {
            const int col = bn * 128 + wx * 64 + nt * 8 + rid * 2;
            const float b0v = bias[col];
            const float b1v = bias[col + 1];
            float2 r0, r1;
            r0.x = cacc[mt][nt][0] + b0v; r0.y = cacc[mt][nt][1] + b1v;
            r1.x = cacc[mt][nt][2] + b0v; r1.y = cacc[mt][nt][3] + b1v;
            if (round_out) {
                r0.x = __uint_as_float(f2tf32(r0.x));
                r0.y = __uint_as_float(f2tf32(r0.y));
                r1.x = __uint_as_float(f2tf32(r1.x));
                r1.y = __uint_as_float(f2tf32(r1.y));
            }
            *(float2*)(C + (size_t)row0 * HID + col)       = r0;
            *(float2*)(C + (size_t)(row0 + 8) * HID + col) = r1;
        }
    }
}

// ===========================================================================
// Tensor-core flash attention v3: q-tile 128, warp-local softmax,
// key-chunk 32 -> smem 87KB -> 2 CTAs/SM (occ 25%).
// Warp w owns rows 16w..16w+15 for S (full 32 chunk cols) and PV (d=128).
// Q fragments live in registers for all 32 chunks.
// ===========================================================================
#define KP 132   // K / Q-stage pitch (must be 4 mod 32)
#define VP 136   // V pitch (must be 8 mod 32)
#define PP2 36   // P pitch (32 cols)
#define CKEYS 32 // keys per chunk

#define SM_KS   0                            // 2 stages: 2*32*KP = 8448
#define SM_VS   (2 * CKEYS * KP)             // 2 stages: 2*32*VP = 8704
#define SM_PS   (SM_VS + 2 * CKEYS * VP)     // 128*PP2 = 4608
#define ATTN_FLOATS (SM_PS + 128 * PP2)      // 21760 floats
#define ATTN_SMEM   (ATTN_FLOATS * 4)        // 87040 B

__global__ __launch_bounds__(256) void attn_kernel(
    const float* __restrict__ qlin, const float* __restrict__ klin,
    const float* __restrict__ vlin, float* __restrict__ ctx)
{
    extern __shared__ __align__(16) float sm[];
    float* Ks = sm + SM_KS;
    float* Vs = sm + SM_VS;
    float* Ps = sm + SM_PS;

    const int tid  = threadIdx.x;
    const int wid  = tid >> 5;
    const int lane = tid & 31;
    const int qid  = lane >> 2;
    const int rid  = lane & 3;
    const int rlo  = 16 * wid + qid;
    const int rhi  = rlo + 8;

    const int gt = blockIdx.x;          // 0..7, q-tile of 128 groups
    const int h  = blockIdx.y;
    const int b  = blockIdx.z;
    const int g0 = gt * 128;
    const size_t bbase = (size_t)b * SEQ * HID;
    const float* qb = qlin + bbase;
    const float* kb = klin + bbase;
    const float* vb = vlin + bbase;
    const int hcol = h * 64;

    const uint32_t sbase = smem_u32(sm);

    // --- stage Q (128 rows x 128 floats, pitch KP) across the smem union ---
    // (fits: 128*KP = 16896 < 21760 total floats; K/V loads start only after
    //  fragment extraction + barrier below)
#pragma unroll
    for (int p = 0; p < 16; p++) {
        const int idx = tid + p * 256;
        const int i   = idx >> 5;
        const int d4  = (idx & 31) * 4;
        const int par = d4 >> 6;
        const int cc  = d4 & 63;
        cp16(sbase + (uint32_t)(i * KP + d4) * 4u,
             qb + (size_t)(2 * (g0 + i) + par) * HID + hcol + cc);
    }
    CP_COMMIT();
    CP_WAIT0();
    __syncthreads();

    // --- extract Q fragments to registers (reused for all chunks) ---
    uint32_t qfr[16][4];
#pragma unroll
    for (int ks = 0; ks < 16; ks++) {
        const int k0 = ks * 8;
        qfr[ks][0] = __float_as_uint(sm[rlo * KP + k0 + rid    ]);
        qfr[ks][1] = __float_as_uint(sm[rhi * KP + k0 + rid    ]);
        qfr[ks][2] = __float_as_uint(sm[rlo * KP + k0 + rid + 4]);
        qfr[ks][3] = __float_as_uint(sm[rhi * KP + k0 + rid + 4]);
    }
    __syncthreads();   // all warps done reading Q before K/V overwrite

    auto loadKV = [&](int c, int s) {
        const uint32_t ka = sbase + (uint32_t)(SM_KS + s * CKEYS * KP) * 4u;
        const uint32_t va = sbase + (uint32_t)(SM_VS + s * CKEYS * VP) * 4u;
        const int j0 = c * CKEYS;
#pragma unroll
        for (int p = 0; p < 4; p++) {
            const int idx = tid + p * 256;
            const int j   = idx >> 5;          // 0..31
            const int d4  = (idx & 31) * 4;
            const int par = d4 >> 6;
            const int cc  = d4 & 63;
            const size_t gs = (size_t)(2 * (j0 + j) + par) * HID + hcol + cc;
            cp16(ka + (uint32_t)(j * KP + d4) * 4u, kb + gs);
            cp16(va + (uint32_t)(j * VP + d4) * 4u, vb + gs);
        }
        CP_COMMIT();
    };

    loadKV(0, 0);

    float m_lo = -1e30f, m_hi = -1e30f, l_lo = 0.0f, l_hi = 0.0f;
    float o[16][4];
#pragma unroll
    for (int nt = 0; nt < 16; nt++)
#pragma unroll
        for (int e = 0; e < 4; e++) o[nt][e] = 0.0f;

    for (int c = 0; c < 32; c++) {
        const int s = c & 1;
        CP_WAIT0();
        __syncthreads();               // chunk c resident; all warps past c-1
        if (c + 1 < 32) loadKV(c + 1, s ^ 1);

        const float* Kst = Ks + s * CKEYS * KP;
        const float* Vst = Vs + s * CKEYS * VP;

        // --- S = Q K^T: this warp rows rlo/rhi+, 32 chunk cols ---
        float sacc[4][4];
#pragma unroll
        for (int nt = 0; nt < 4; nt++)
#pragma unroll
            for (int e = 0; e < 4; e++) sacc[nt][e] = 0.0f;

#pragma unroll
        for (int ks = 0; ks < 16; ks++) {
            const int k0 = ks * 8;
            uint32_t bfr[4][2];
#pragma unroll
            for (int nt = 0; nt < 4; nt++) {
                const int n = nt * 8 + qid;
                bfr[nt][0] = __float_as_uint(Kst[n * KP + k0 + rid    ]);
                bfr[nt][1] = __float_as_uint(Kst[n * KP + k0 + rid + 4]);
            }
#pragma unroll
            for (int nt = 0; nt < 4; nt++)
                mma_tf32(sacc[nt], qfr[ks], bfr[nt]);
        }

        // --- warp-local online softmax (rows rlo, rhi) ---
        float vlo = -1e30f, vhi = -1e30f;
#pragma unroll
        for (int nt = 0; nt < 4; nt++) {
            sacc[nt][0] *= SCALE; sacc[nt][1] *= SCALE;
            sacc[nt][2] *= SCALE; sacc[nt][3] *= SCALE;
            vlo = fmaxf(vlo, fmaxf(sacc[nt][0], sacc[nt][1]));
            vhi = fmaxf(vhi, fmaxf(sacc[nt][2], sacc[nt][3]));
        }
        vlo = fmaxf(vlo, __shfl_xor_sync(0xffffffffu, vlo, 1));
        vlo = fmaxf(vlo, __shfl_xor_sync(0xffffffffu, vlo, 2));
        vhi = fmaxf(vhi, __shfl_xor_sync(0xffffffffu, vhi, 1));
        vhi = fmaxf(vhi, __shfl_xor_sync(0xffffffffu, vhi, 2));

        const float mn_lo = fmaxf(m_lo, vlo);
        const float mn_hi = fmaxf(m_hi, vhi);
        const float al_lo = __expf(m_lo - mn_lo);
        const float al_hi = __expf(m_hi - mn_hi);
        m_lo = mn_lo; m_hi = mn_hi;

        float slo = 0.0f, shi = 0.0f;
#pragma unroll
        for (int nt = 0; nt < 4; nt++) {
            float p0 = __expf(sacc[nt][0] - mn_lo);
            float p1 = __expf(sacc[nt][1] - mn_lo);
            float p2 = __expf(sacc[nt][2] - mn_hi);
            float p3 = __expf(sacc[nt][3] - mn_hi);
            slo += p0 + p1;
            shi += p2 + p3;
            const int col = nt * 8 + rid * 2;
            *(float2*)&Ps[rlo * PP2 + col] =
                make_float2(__uint_as_float(f2tf32(p0)), __uint_as_float(f2tf32(p1)));
            *(float2*)&Ps[rhi * PP2 + col] =
                make_float2(__uint_as_float(f2tf32(p2)), __uint_as_float(f2tf32(p3)));
        }
        slo += __shfl_xor_sync(0xffffffffu, slo, 1);
        slo += __shfl_xor_sync(0xffffffffu, slo, 2);
        shi += __shfl_xor_sync(0xffffffffu, shi, 1);
        shi += __shfl_xor_sync(0xffffffffu, shi, 2);
        l_lo = l_lo * al_lo + slo;
        l_hi = l_hi * al_hi + shi;

        __syncwarp();   // this warp's P rows written before PV reads them

        // --- rescale O, accumulate P @ V (rows rlo/rhi, full d=128) ---
#pragma unroll
        for (int nt = 0; nt < 16; nt++) {
            o[nt][0] *= al_lo; o[nt][1] *= al_lo;
            o[nt][2] *= al_hi; o[nt][3] *= al_hi;
        }
#pragma unroll
        for (int ks = 0; ks < 4; ks++) {
            const int kj = ks * 8;
            uint32_t afr[4];
            afr[0] = __float_as_uint(Ps[rlo * PP2 + kj + rid    ]);
            afr[1] = __float_as_uint(Ps[rhi * PP2 + kj + rid    ]);
            afr[2] = __float_as_uint(Ps[rlo * PP2 + kj + rid + 4]);
            afr[3] = __float_as_uint(Ps[rhi * PP2 + kj + rid + 4]);
            uint32_t bfr[16][2];
#pragma unroll
            for (int nt = 0; nt < 16; nt++) {
                const int n = nt * 8 + qid;
                bfr[nt][0] = __float_as_uint(Vst[(kj + rid    ) * VP + n]);
                bfr[nt][1] = __float_as_uint(Vst[(kj + rid + 4) * VP + n]);
            }
#pragma unroll
            for (int nt = 0; nt < 16; nt++)
                mma_tf32(o[nt], afr, bfr[nt]);
        }
        // stage s is only overwritten by the load issued at iteration c+1,
        // after its leading __syncthreads.
    }

    // --- epilogue: normalize, round tf32, scatter to linear ctx layout ---
    float* cb = ctx + bbase;
    const float inv_lo = 1.0f / l_lo;
    const float inv_hi = 1.0f / l_hi;
    const int orow_lo = 2 * (g0 + rlo) + (h >> 3);
    const int orow_hi = 2 * (g0 + rhi) + (h >> 3);
#pragma unroll
    for (int nt = 0; nt < 16; nt++) {
        const int d = nt * 8 + rid * 2;
        const int ocol = (h & 7) * 128 + d;
        *(float2*)(cb + (size_t)orow_lo * HID + ocol) = make_float2(
            __uint_as_float(f2tf32(o[nt][0] * inv_lo)),
            __uint_as_float(f2tf32(o[nt][1] * inv_lo)));
        *(float2*)(cb + (size_t)orow_hi * HID + ocol) = make_float2(
            __uint_as_float(f2tf32(o[nt][2] * inv_hi)),
            __uint_as_float(f2tf32(o[nt][3] * inv_hi)));
    }
}

// ---------------------------------------------------------------------------
extern "C" void kernel_launch(void* const* d_in, const int* in_sizes, int n_in,
                              void* d_out, int out_size)
{
    const float* x  = (const float*)d_in[0];
    const float* Wq = (const float*)d_in[1];
    const float* bq = (const float*)d_in[2];
    const float* Wk = (const float*)d_in[3];
    const float* bk = (const float*)d_in[4];
    const float* Wv = (const float*)d_in[5];
    const float* bv = (const float*)d_in[6];
    const float* Wo = (const float*)d_in[7];
    const float* bo = (const float*)d_in[8];
    float* out = (float*)d_out;

    float *q, *k, *v, *ctx, *xr, *wq, *wk, *wv, *wo;
    cudaGetSymbolAddress((void**)&q,   g_q);
    cudaGetSymbolAddress((void**)&k,   g_k);
    cudaGetSymbolAddress((void**)&v,   g_v);
    cudaGetSymbolAddress((void**)&ctx, g_ctx);
    cudaGetSymbolAddress((void**)&xr,  g_x);
    cudaGetSymbolAddress((void**)&wq,  g_wq);
    cudaGetSymbolAddress((void**)&wk,  g_wk);
    cudaGetSymbolAddress((void**)&wv,  g_wv);
    cudaGetSymbolAddress((void**)&wo,  g_wo);

    // pre-round input and weights to tf32
    const int nx4 = (M_TOT * HID) / 4;
    const int nw4 = (HID * HID) / 4;
    round_tf32_kernel<<<(nx4 + 255) / 256, 256>>>(x, xr, nx4);
    round_w_kernel<<<dim3((nw4 + 255) / 256, 4), 256>>>(
        Wq, Wk, Wv, Wo, wq, wk, wv, wo, nw4);

    cudaFuncSetAttribute(gemm_tf32_3,
                         cudaFuncAttributeMaxDynamicSharedMemorySize, GEMM_SMEM);
    cudaFuncSetAttribute(attn_kernel,
                         cudaFuncAttributeMaxDynamicSharedMemorySize, ATTN_SMEM);

    // fused Q/K/V projection (grid.z picks weight/bias/output)
    gemm_tf32_3<<<dim3(HID / 128, M_TOT / 128, 3), 128, GEMM_SMEM>>>(
        xr, wq, wk, wv, bq, bk, bv, q, k, v, 1);

    attn_kernel<<<dim3(NG / 128, NH, BATCH), 256, ATTN_SMEM>>>(q, k, v, ctx);

    // output projection
    gemm_tf32_3<<<dim3(HID / 128, M_TOT / 128, 1), 128, GEMM_SMEM>>>(
        ctx, wo, wo, wo, bo, bo, bo, out, out, out, 0);
}